// round 1
// baseline (speedup 1.0000x reference)
#include <cuda_runtime.h>
#include <math.h>

// Problem constants
#define BATCH 2
#define NPTS 1024
#define NUM_BINS 22
#define TDIM 16
#define MAX_DIST 40.0f
#define LN_EPS 1e-5f

// Precomputed per-bin output rows: T[bin][d] = relu(LN(W[bin]+b)*gamma+beta)
__device__ float g_table[NUM_BINS * TDIM];

// ---------------------------------------------------------------------------
// Kernel 1: build the 22x16 table. One warp, one thread per bin.
// ---------------------------------------------------------------------------
__global__ void build_table_kernel(const float* __restrict__ W,
                                   const float* __restrict__ b,
                                   const float* __restrict__ gamma,
                                   const float* __restrict__ beta) {
    int bin = threadIdx.x;
    if (bin >= NUM_BINS) return;

    float h[TDIM];
    float sum = 0.0f;
#pragma unroll
    for (int d = 0; d < TDIM; ++d) {
        h[d] = W[bin * TDIM + d] + b[d];
        sum += h[d];
    }
    float mu = sum * (1.0f / TDIM);
    float var = 0.0f;
#pragma unroll
    for (int d = 0; d < TDIM; ++d) {
        float c = h[d] - mu;
        var += c * c;
    }
    var *= (1.0f / TDIM);
    float inv = rsqrtf(var + LN_EPS);
#pragma unroll
    for (int d = 0; d < TDIM; ++d) {
        float v = (h[d] - mu) * inv * gamma[d] + beta[d];
        g_table[bin * TDIM + d] = fmaxf(v, 0.0f);
    }
}

// ---------------------------------------------------------------------------
// Kernel 2: per-pair distance -> bin -> table lookup -> scaled store.
// 4 threads per pair (each stores one float4): warp writes 512B contiguous.
// Block = 256 threads = 64 pairs/iter, 4 iters => 256 j's per block.
// Grid = (N/256, N, B).
// ---------------------------------------------------------------------------
__global__ __launch_bounds__(256)
void encode_kernel(const float* __restrict__ coords,
                   const float* __restrict__ conf,
                   float* __restrict__ out) {
    __shared__ float sT[NUM_BINS * TDIM];

    const int tid = threadIdx.x;
    for (int t = tid; t < NUM_BINS * TDIM; t += 256) sT[t] = g_table[t];

    const int i     = blockIdx.y;
    const int batch = blockIdx.z;

    const float* ci_ptr = coords + ((size_t)batch * NPTS + i) * 3;
    const float xi = ci_ptr[0], yi = ci_ptr[1], zi = ci_ptr[2];
    const float ci = conf[batch * NPTS + i];

    __syncthreads();

    const int p = tid >> 2;   // pair slot within 64
    const int k = tid & 3;    // which float4 of the 16-vector
    const int j_base = blockIdx.x * 256;

    float* outrow = out + (((size_t)batch * NPTS + i) * NPTS) * TDIM;

    const float inv_w = (float)(NUM_BINS - 1) / MAX_DIST;  // 21/40

#pragma unroll
    for (int it = 0; it < 4; ++it) {
        const int j = j_base + it * 64 + p;

        const float* cj_ptr = coords + ((size_t)batch * NPTS + j) * 3;
        const float dx = xi - cj_ptr[0];
        const float dy = yi - cj_ptr[1];
        const float dz = zi - cj_ptr[2];
        const float cj = conf[batch * NPTS + j];

        const float dist = sqrtf(fmaf(dx, dx, fmaf(dy, dy, fmaf(dz, dz, 1e-8f))));

        int bin;
        if (ci > 0.0f && cj > 0.0f) {
            bin = (int)(dist * inv_w) + 1;          // edges strictly below dist
            bin = (bin > NUM_BINS - 2) ? (NUM_BINS - 2) : bin;
        } else {
            bin = NUM_BINS - 1;                     // no-template bin
        }

        const float s = fminf(ci, cj);
        float4 v = *(const float4*)&sT[bin * TDIM + k * 4];
        v.x *= s; v.y *= s; v.z *= s; v.w *= s;
        *(float4*)(outrow + (size_t)j * TDIM + k * 4) = v;
    }
}

// ---------------------------------------------------------------------------
// Launch
// ---------------------------------------------------------------------------
extern "C" void kernel_launch(void* const* d_in, const int* in_sizes, int n_in,
                              void* d_out, int out_size) {
    const float* coords = (const float*)d_in[0];  // (B,N,3)
    const float* conf   = (const float*)d_in[1];  // (B,N)
    const float* W      = (const float*)d_in[2];  // (22,16)
    const float* b      = (const float*)d_in[3];  // (16,)
    const float* gamma  = (const float*)d_in[4];  // (16,)
    const float* beta   = (const float*)d_in[5];  // (16,)
    float* out = (float*)d_out;                   // (B,N,N,16)

    build_table_kernel<<<1, 32>>>(W, b, gamma, beta);

    dim3 grid(NPTS / 256, NPTS, BATCH);
    encode_kernel<<<grid, 256>>>(coords, conf, out);
}